// round 6
// baseline (speedup 1.0000x reference)
#include <cuda_runtime.h>

// Problem constants
#define BB 8192   // batch
#define II 1024   // input size (K)
#define HH 512    // hidden per expert
#define EE 16     // experts
#define TT 4      // tasks
#define NN (EE*HH) // 8192 GEMM columns

// Scratch: softmax gates g[b][t][e]  (8192*64 floats = 2 MB)
__device__ float g_gate_buf[BB * TT * EE];

// ---------------------------------------------------------------------------
// Gate kernel: logits = x @ Wg^T + bg  -> softmax over E -> g_gate_buf
// Also initializes out[t,b] = bf[t].
// Grid: 128 blocks x 256 threads; each block handles 64 batch rows, all 64
// (t,e) columns, K=1024.
// ---------------------------------------------------------------------------
__global__ __launch_bounds__(256) void gate_kernel(
    const float* __restrict__ x, const float* __restrict__ Wg,
    const float* __restrict__ bg, const float* __restrict__ bf,
    float* __restrict__ out)
{
    __shared__ float As[16][68];   // x tile, [k][m]
    __shared__ float Bs[16][68];   // Wg tile, [k][n]
    __shared__ float Ls[64][68];   // logits

    const int tid = threadIdx.x;
    const int tx = tid & 15, ty = tid >> 4;
    const int bm = blockIdx.x * 64;
    const int lrow = tid >> 2;          // 0..63
    const int lkq  = (tid & 3) << 2;    // 0,4,8,12

    float acc[4][4];
    #pragma unroll
    for (int i = 0; i < 4; ++i)
        #pragma unroll
        for (int j = 0; j < 4; ++j) acc[i][j] = 0.f;

    const float* pA = x  + (long)(bm + lrow) * II + lkq;
    const float* pB = Wg + (long)lrow * II + lkq;

    for (int k0 = 0; k0 < II; k0 += 16) {
        float4 va = *(const float4*)(pA + k0);
        float4 vb = *(const float4*)(pB + k0);
        As[lkq+0][lrow] = va.x; As[lkq+1][lrow] = va.y;
        As[lkq+2][lrow] = va.z; As[lkq+3][lrow] = va.w;
        Bs[lkq+0][lrow] = vb.x; Bs[lkq+1][lrow] = vb.y;
        Bs[lkq+2][lrow] = vb.z; Bs[lkq+3][lrow] = vb.w;
        __syncthreads();
        #pragma unroll
        for (int kk = 0; kk < 16; ++kk) {
            float a[4], b[4];
            #pragma unroll
            for (int i = 0; i < 4; ++i) a[i] = As[kk][ty*4+i];
            #pragma unroll
            for (int j = 0; j < 4; ++j) b[j] = Bs[kk][tx*4+j];
            #pragma unroll
            for (int i = 0; i < 4; ++i)
                #pragma unroll
                for (int j = 0; j < 4; ++j)
                    acc[i][j] = fmaf(a[i], b[j], acc[i][j]);
        }
        __syncthreads();
    }

    #pragma unroll
    for (int i = 0; i < 4; ++i)
        #pragma unroll
        for (int j = 0; j < 4; ++j)
            Ls[ty*4+i][tx*4+j] = acc[i][j] + bg[tx*4+j];
    __syncthreads();

    // Softmax: one thread per (row, t) pair
    {
        const int row = tid >> 2, t = tid & 3;
        const float* L = &Ls[row][t*16];
        float m = L[0];
        #pragma unroll
        for (int e = 1; e < 16; ++e) m = fmaxf(m, L[e]);
        float ex[16], s = 0.f;
        #pragma unroll
        for (int e = 0; e < 16; ++e) { ex[e] = __expf(L[e] - m); s += ex[e]; }
        const float inv = 1.f / s;
        const int b = bm + row;
        #pragma unroll
        for (int e = 0; e < 16; ++e)
            g_gate_buf[b*64 + t*16 + e] = ex[e] * inv;
        out[t*BB + b] = bf[t];
    }
}

// ---------------------------------------------------------------------------
// Expert GEMM + fused epilogue.
// C[m][n] = x[m,:] . We[n,:]  (n = e*512 + h), then
//   v = relu(C + be[e,h]);  partial[t] += g[m,t,e] * v * Wf[t,h]
// reduced over the 128-wide h-chunk in smem, atomicAdd into out[t,m].
// Tiles: BM=128, BN=128, BK=16. 256 threads, 8x8/thread with packed f32x2 FMA.
// ---------------------------------------------------------------------------
#define FMA2(d, a, b) asm("fma.rn.f32x2 %0, %1, %2, %0;" : "+l"(d) : "l"(a), "l"(b))

__global__ __launch_bounds__(256, 2) void expert_kernel(
    const float* __restrict__ x, const float* __restrict__ We,
    const float* __restrict__ be, const float* __restrict__ Wf,
    float* __restrict__ out)
{
    __shared__ float As[16][132];     // x tile   [k][m]
    __shared__ float Bs[16][132];     // We tile  [k][n]
    __shared__ float wf_s[4][128];    // Wf[t][h-chunk]
    __shared__ float be_s[128];       // be[e][h-chunk]
    __shared__ float g_s[128][4];     // g[row][t] for fixed e
    __shared__ float red[128][17];    // cross-thread reduction

    const int tid = threadIdx.x;
    const int tx = tid & 15, ty = tid >> 4;
    const int bn = blockIdx.x * 128;
    const int bm = blockIdx.y * 128;
    const int e  = bn >> 9;            // expert index (constant per block)
    const int h0 = bn & (HH - 1);      // h offset within expert

    // Prologue smem fills (visibility guaranteed by first mainloop sync)
    for (int i = tid; i < 512; i += 256)
        wf_s[i>>7][i&127] = Wf[(i>>7)*HH + h0 + (i&127)];
    for (int i = tid; i < 128; i += 256)
        be_s[i] = be[e*HH + h0 + i];
    for (int i = tid; i < 512; i += 256)
        g_s[i>>2][i&3] = g_gate_buf[(bm + (i>>2))*64 + (i&3)*16 + e];

    const int lrow = tid >> 2;          // 0..63
    const int lkq  = (tid & 3) << 2;    // 0,4,8,12
    const float* pA = x  + (long)(bm + lrow) * II + lkq;
    const float* pB = We + (long)(bn + lrow) * II + lkq;

    unsigned long long acc[8][4];       // packed pairs along n (cols 2p,2p+1)
    #pragma unroll
    for (int i = 0; i < 8; ++i)
        #pragma unroll
        for (int p = 0; p < 4; ++p) acc[i][p] = 0ull;

    // Software pipeline: prefetch tile k0 into registers
    float4 ra0 = *(const float4*)(pA);
    float4 ra1 = *(const float4*)(pA + 64*II);
    float4 rb0 = *(const float4*)(pB);
    float4 rb1 = *(const float4*)(pB + 64*II);

    for (int k0 = 0; k0 < II; k0 += 16) {
        As[lkq+0][lrow]    = ra0.x; As[lkq+1][lrow]    = ra0.y;
        As[lkq+2][lrow]    = ra0.z; As[lkq+3][lrow]    = ra0.w;
        As[lkq+0][lrow+64] = ra1.x; As[lkq+1][lrow+64] = ra1.y;
        As[lkq+2][lrow+64] = ra1.z; As[lkq+3][lrow+64] = ra1.w;
        Bs[lkq+0][lrow]    = rb0.x; Bs[lkq+1][lrow]    = rb0.y;
        Bs[lkq+2][lrow]    = rb0.z; Bs[lkq+3][lrow]    = rb0.w;
        Bs[lkq+0][lrow+64] = rb1.x; Bs[lkq+1][lrow+64] = rb1.y;
        Bs[lkq+2][lrow+64] = rb1.z; Bs[lkq+3][lrow+64] = rb1.w;
        __syncthreads();

        if (k0 + 16 < II) {  // prefetch next tile (overlaps with compute)
            ra0 = *(const float4*)(pA + k0 + 16);
            ra1 = *(const float4*)(pA + 64*II + k0 + 16);
            rb0 = *(const float4*)(pB + k0 + 16);
            rb1 = *(const float4*)(pB + 64*II + k0 + 16);
        }

        #pragma unroll
        for (int kk = 0; kk < 16; ++kk) {
            const float4 a0 = *(const float4*)&As[kk][ty*8];
            const float4 a1 = *(const float4*)&As[kk][ty*8+4];
            const ulonglong2 b0 = *(const ulonglong2*)&Bs[kk][tx*8];
            const ulonglong2 b1 = *(const ulonglong2*)&Bs[kk][tx*8+4];
            const float av[8] = {a0.x, a0.y, a0.z, a0.w, a1.x, a1.y, a1.z, a1.w};
            #pragma unroll
            for (int i = 0; i < 8; ++i) {
                unsigned long long ad;
                const unsigned int au = __float_as_uint(av[i]);
                asm("mov.b64 %0, {%1, %1};" : "=l"(ad) : "r"(au));
                FMA2(acc[i][0], ad, b0.x);
                FMA2(acc[i][1], ad, b0.y);
                FMA2(acc[i][2], ad, b1.x);
                FMA2(acc[i][3], ad, b1.y);
            }
        }
        __syncthreads();
    }

    // ---- Fused epilogue: relu(+be), dot with Wf per task, scale by gate ----
    float pt[8][4];
    #pragma unroll
    for (int i = 0; i < 8; ++i) {
        float v[8];
        #pragma unroll
        for (int p = 0; p < 4; ++p) {
            unsigned int lo, hi;
            asm("mov.b64 {%0, %1}, %2;" : "=r"(lo), "=r"(hi) : "l"(acc[i][p]));
            v[2*p]   = __uint_as_float(lo);
            v[2*p+1] = __uint_as_float(hi);
        }
        #pragma unroll
        for (int j = 0; j < 8; ++j)
            v[j] = fmaxf(v[j] + be_s[tx*8+j], 0.f);
        #pragma unroll
        for (int t = 0; t < 4; ++t) {
            float p = 0.f;
            #pragma unroll
            for (int j = 0; j < 8; ++j)
                p = fmaf(v[j], wf_s[t][tx*8+j], p);
            pt[i][t] = p * g_s[ty*8+i][t];
        }
    }

    // Reduce across the 16 column-thread-groups per row; 4 passes over t
    #pragma unroll
    for (int t = 0; t < 4; ++t) {
        #pragma unroll
        for (int i = 0; i < 8; ++i)
            red[ty*8+i][tx] = pt[i][t];
        __syncthreads();
        if (tid < 128) {
            float s = 0.f;
            #pragma unroll
            for (int q = 0; q < 16; ++q) s += red[tid][q];
            atomicAdd(&out[t*BB + bm + tid], s);
        }
        __syncthreads();
    }
}

// ---------------------------------------------------------------------------
// Launch. Inputs (metadata order): x, We, be, Wg, bg, Wf, bf. Output f32 [T,B,1].
// ---------------------------------------------------------------------------
extern "C" void kernel_launch(void* const* d_in, const int* in_sizes, int n_in,
                              void* d_out, int out_size)
{
    const float* x  = (const float*)d_in[0];
    const float* We = (const float*)d_in[1];
    const float* be = (const float*)d_in[2];
    const float* Wg = (const float*)d_in[3];
    const float* bg = (const float*)d_in[4];
    const float* Wf = (const float*)d_in[5];
    const float* bf = (const float*)d_in[6];
    float* out = (float*)d_out;

    // 1) gates + softmax + out init (out[t,b] = bf[t])
    gate_kernel<<<BB/64, 256>>>(x, Wg, bg, bf, out);

    // 2) expert GEMM with fused relu/Wf/gate epilogue, accumulating into out
    dim3 grid(NN/128, BB/128);   // 64 x 64 blocks
    expert_kernel<<<grid, 256>>>(x, We, be, Wf, out);
}

// round 7
// speedup vs baseline: 1.2181x; 1.2181x over previous
#include <cuda_runtime.h>

// Problem constants
#define BB 8192   // batch
#define II 1024   // input size (K)
#define HH 512    // hidden per expert
#define EE 16     // experts
#define TT 4      // tasks
#define NN (EE*HH) // 8192 GEMM columns

// Scratch: softmax gates g[b][t][e]  (8192*64 floats = 2 MB)
__device__ float g_gate_buf[BB * TT * EE];

// ---------------------------------------------------------------------------
// Gate kernel: logits = x @ Wg^T + bg  -> softmax over E -> g_gate_buf
// Also initializes out[t,b] = bf[t].
// ---------------------------------------------------------------------------
__global__ __launch_bounds__(256) void gate_kernel(
    const float* __restrict__ x, const float* __restrict__ Wg,
    const float* __restrict__ bg, const float* __restrict__ bf,
    float* __restrict__ out)
{
    __shared__ float As[16][68];   // x tile, [k][m]
    __shared__ float Bs[16][68];   // Wg tile, [k][n]
    __shared__ float Ls[64][68];   // logits

    const int tid = threadIdx.x;
    const int tx = tid & 15, ty = tid >> 4;
    const int bm = blockIdx.x * 64;
    const int lrow = tid >> 2;          // 0..63
    const int lkq  = (tid & 3) << 2;    // 0,4,8,12

    float acc[4][4];
    #pragma unroll
    for (int i = 0; i < 4; ++i)
        #pragma unroll
        for (int j = 0; j < 4; ++j) acc[i][j] = 0.f;

    const float* pA = x  + (long)(bm + lrow) * II + lkq;
    const float* pB = Wg + (long)lrow * II + lkq;

    for (int k0 = 0; k0 < II; k0 += 16) {
        float4 va = *(const float4*)(pA + k0);
        float4 vb = *(const float4*)(pB + k0);
        As[lkq+0][lrow] = va.x; As[lkq+1][lrow] = va.y;
        As[lkq+2][lrow] = va.z; As[lkq+3][lrow] = va.w;
        Bs[lkq+0][lrow] = vb.x; Bs[lkq+1][lrow] = vb.y;
        Bs[lkq+2][lrow] = vb.z; Bs[lkq+3][lrow] = vb.w;
        __syncthreads();
        #pragma unroll
        for (int kk = 0; kk < 16; ++kk) {
            float a[4], b[4];
            #pragma unroll
            for (int i = 0; i < 4; ++i) a[i] = As[kk][ty*4+i];
            #pragma unroll
            for (int j = 0; j < 4; ++j) b[j] = Bs[kk][tx*4+j];
            #pragma unroll
            for (int i = 0; i < 4; ++i)
                #pragma unroll
                for (int j = 0; j < 4; ++j)
                    acc[i][j] = fmaf(a[i], b[j], acc[i][j]);
        }
        __syncthreads();
    }

    #pragma unroll
    for (int i = 0; i < 4; ++i)
        #pragma unroll
        for (int j = 0; j < 4; ++j)
            Ls[ty*4+i][tx*4+j] = acc[i][j] + bg[tx*4+j];
    __syncthreads();

    // Softmax: one thread per (row, t) pair
    {
        const int row = tid >> 2, t = tid & 3;
        const float* L = &Ls[row][t*16];
        float m = L[0];
        #pragma unroll
        for (int e = 1; e < 16; ++e) m = fmaxf(m, L[e]);
        float ex[16], s = 0.f;
        #pragma unroll
        for (int e = 0; e < 16; ++e) { ex[e] = __expf(L[e] - m); s += ex[e]; }
        const float inv = 1.f / s;
        const int b = bm + row;
        #pragma unroll
        for (int e = 0; e < 16; ++e)
            g_gate_buf[b*64 + t*16 + e] = ex[e] * inv;
        out[t*BB + b] = bf[t];
    }
}

// ---------------------------------------------------------------------------
// Expert GEMM + fused epilogue.
// Column remap per thread: cols { tx*4+0..3 } and { 64+tx*4+0..3 } so every
// B-fragment LDS.128 has lane-stride 16B -> conflict-free (was 2-way at tx*8).
// ---------------------------------------------------------------------------
#define FMA2(d, a, b) asm("fma.rn.f32x2 %0, %1, %2, %0;" : "+l"(d) : "l"(a), "l"(b))

__global__ __launch_bounds__(256, 2) void expert_kernel(
    const float* __restrict__ x, const float* __restrict__ We,
    const float* __restrict__ be, const float* __restrict__ Wf,
    float* __restrict__ out)
{
    __shared__ float As[16][132];     // x tile   [k][m]
    __shared__ float Bs[16][132];     // We tile  [k][n]
    __shared__ float wf_s[4][128];    // Wf[t][h-chunk]
    __shared__ float be_s[128];       // be[e][h-chunk]
    __shared__ float g_s[128][4];     // g[row][t] for fixed e
    __shared__ float red[128][17];    // cross-thread reduction

    const int tid = threadIdx.x;
    const int tx = tid & 15, ty = tid >> 4;
    const int bn = blockIdx.x * 128;
    const int bm = blockIdx.y * 128;
    const int e  = bn >> 9;            // expert index (constant per block)
    const int h0 = bn & (HH - 1);      // h offset within expert

    // Prologue smem fills (visibility guaranteed by first mainloop sync)
    for (int i = tid; i < 512; i += 256)
        wf_s[i>>7][i&127] = Wf[(i>>7)*HH + h0 + (i&127)];
    for (int i = tid; i < 128; i += 256)
        be_s[i] = be[e*HH + h0 + i];
    for (int i = tid; i < 512; i += 256)
        g_s[i>>2][i&3] = g_gate_buf[(bm + (i>>2))*64 + (i&3)*16 + e];

    const int lrow = tid >> 2;          // 0..63
    const int lkq  = (tid & 3) << 2;    // 0,4,8,12
    const float* pA = x  + (long)(bm + lrow) * II + lkq;
    const float* pB = We + (long)(bn + lrow) * II + lkq;

    // acc[i][p]: row ty*8+i; p=0 -> cols (tx*4+0, tx*4+1), p=1 -> (tx*4+2, tx*4+3)
    //            p=2 -> cols (64+tx*4+0, 64+tx*4+1), p=3 -> (64+tx*4+2, 64+tx*4+3)
    unsigned long long acc[8][4];
    #pragma unroll
    for (int i = 0; i < 8; ++i)
        #pragma unroll
        for (int p = 0; p < 4; ++p) acc[i][p] = 0ull;

    // Software pipeline: prefetch tile k0 into registers
    float4 ra0 = *(const float4*)(pA);
    float4 ra1 = *(const float4*)(pA + 64*II);
    float4 rb0 = *(const float4*)(pB);
    float4 rb1 = *(const float4*)(pB + 64*II);

    for (int k0 = 0; k0 < II; k0 += 16) {
        As[lkq+0][lrow]    = ra0.x; As[lkq+1][lrow]    = ra0.y;
        As[lkq+2][lrow]    = ra0.z; As[lkq+3][lrow]    = ra0.w;
        As[lkq+0][lrow+64] = ra1.x; As[lkq+1][lrow+64] = ra1.y;
        As[lkq+2][lrow+64] = ra1.z; As[lkq+3][lrow+64] = ra1.w;
        Bs[lkq+0][lrow]    = rb0.x; Bs[lkq+1][lrow]    = rb0.y;
        Bs[lkq+2][lrow]    = rb0.z; Bs[lkq+3][lrow]    = rb0.w;
        Bs[lkq+0][lrow+64] = rb1.x; Bs[lkq+1][lrow+64] = rb1.y;
        Bs[lkq+2][lrow+64] = rb1.z; Bs[lkq+3][lrow+64] = rb1.w;
        __syncthreads();

        if (k0 + 16 < II) {  // prefetch next tile (overlaps with compute)
            ra0 = *(const float4*)(pA + k0 + 16);
            ra1 = *(const float4*)(pA + 64*II + k0 + 16);
            rb0 = *(const float4*)(pB + k0 + 16);
            rb1 = *(const float4*)(pB + 64*II + k0 + 16);
        }

        #pragma unroll
        for (int kk = 0; kk < 16; ++kk) {
            const float4 a0 = *(const float4*)&As[kk][ty*8];
            const float4 a1 = *(const float4*)&As[kk][ty*8+4];
            // Conflict-free B fragments: lane stride = 4 floats (16B)
            const ulonglong2 b0 = *(const ulonglong2*)&Bs[kk][tx*4];
            const ulonglong2 b1 = *(const ulonglong2*)&Bs[kk][64 + tx*4];
            const float av[8] = {a0.x, a0.y, a0.z, a0.w, a1.x, a1.y, a1.z, a1.w};
            #pragma unroll
            for (int i = 0; i < 8; ++i) {
                unsigned long long ad;
                const unsigned int au = __float_as_uint(av[i]);
                asm("mov.b64 %0, {%1, %1};" : "=l"(ad) : "r"(au));
                FMA2(acc[i][0], ad, b0.x);
                FMA2(acc[i][1], ad, b0.y);
                FMA2(acc[i][2], ad, b1.x);
                FMA2(acc[i][3], ad, b1.y);
            }
        }
        __syncthreads();
    }

    // ---- Fused epilogue: relu(+be), dot with Wf per task, scale by gate ----
    // Column of unpacked value j (0..7): j<4 -> tx*4+j ; j>=4 -> 64+tx*4+(j-4)
    float pt[8][4];
    #pragma unroll
    for (int i = 0; i < 8; ++i) {
        float v[8];
        #pragma unroll
        for (int p = 0; p < 4; ++p) {
            unsigned int lo, hi;
            asm("mov.b64 {%0, %1}, %2;" : "=r"(lo), "=r"(hi) : "l"(acc[i][p]));
            v[2*p]   = __uint_as_float(lo);
            v[2*p+1] = __uint_as_float(hi);
        }
        #pragma unroll
        for (int j = 0; j < 8; ++j) {
            const int col = (j < 4) ? (tx*4 + j) : (64 + tx*4 + (j - 4));
            v[j] = fmaxf(v[j] + be_s[col], 0.f);
        }
        #pragma unroll
        for (int t = 0; t < 4; ++t) {
            float p = 0.f;
            #pragma unroll
            for (int j = 0; j < 8; ++j) {
                const int col = (j < 4) ? (tx*4 + j) : (64 + tx*4 + (j - 4));
                p = fmaf(v[j], wf_s[t][col], p);
            }
            pt[i][t] = p * g_s[ty*8+i][t];
        }
    }

    // Reduce across the 16 column-thread-groups per row; 4 passes over t
    #pragma unroll
    for (int t = 0; t < 4; ++t) {
        #pragma unroll
        for (int i = 0; i < 8; ++i)
            red[ty*8+i][tx] = pt[i][t];
        __syncthreads();
        if (tid < 128) {
            float s = 0.f;
            #pragma unroll
            for (int q = 0; q < 16; ++q) s += red[tid][q];
            atomicAdd(&out[t*BB + bm + tid], s);
        }
        __syncthreads();
    }
}

// ---------------------------------------------------------------------------
// Launch. Inputs (metadata order): x, We, be, Wg, bg, Wf, bf. Output f32 [T,B,1].
// ---------------------------------------------------------------------------
extern "C" void kernel_launch(void* const* d_in, const int* in_sizes, int n_in,
                              void* d_out, int out_size)
{
    const float* x  = (const float*)d_in[0];
    const float* We = (const float*)d_in[1];
    const float* be = (const float*)d_in[2];
    const float* Wg = (const float*)d_in[3];
    const float* bg = (const float*)d_in[4];
    const float* Wf = (const float*)d_in[5];
    const float* bf = (const float*)d_in[6];
    float* out = (float*)d_out;

    // 1) gates + softmax + out init (out[t,b] = bf[t])
    gate_kernel<<<BB/64, 256>>>(x, Wg, bg, bf, out);

    // 2) expert GEMM with fused relu/Wf/gate epilogue, accumulating into out
    dim3 grid(NN/128, BB/128);   // 64 x 64 blocks
    expert_kernel<<<grid, 256>>>(x, We, be, Wf, out);
}

// round 11
// speedup vs baseline: 2.2822x; 1.8736x over previous
#include <cuda_runtime.h>
#include <cuda_bf16.h>
#include <stdint.h>

// Problem constants
#define BB 8192   // batch
#define II 1024   // input size (K)
#define HH 512    // hidden per expert
#define EE 16     // experts
#define TT 4      // tasks
#define NN (EE*HH) // 8192 GEMM columns

// Scratch (device globals: allocation-free rule)
__device__ float g_gate_buf[BB * TT * EE];             // 2 MB softmax gates
__device__ __nv_bfloat16 g_x_hi[BB * II];              // 16 MB
__device__ __nv_bfloat16 g_x_lo[BB * II];              // 16 MB
__device__ __nv_bfloat16 g_w_hi[NN * II];              // 16 MB
__device__ __nv_bfloat16 g_w_lo[NN * II];              // 16 MB

// ---------------------------------------------------------------------------
// Split prepass: fp32 -> bf16 hi + bf16 lo (residual)
// ---------------------------------------------------------------------------
__global__ __launch_bounds__(256) void split_kernel(
    const float* __restrict__ src, __nv_bfloat16* __restrict__ hi,
    __nv_bfloat16* __restrict__ lo)
{
    const int i = blockIdx.x * 256 + threadIdx.x;
    float4 v = ((const float4*)src)[i];
    float f[4] = {v.x, v.y, v.z, v.w};
    __nv_bfloat162 h01, h23, l01, l23;
    __nv_bfloat16 h[4], l[4];
    #pragma unroll
    for (int k = 0; k < 4; ++k) {
        h[k] = __float2bfloat16(f[k]);
        l[k] = __float2bfloat16(f[k] - __bfloat162float(h[k]));
    }
    h01.x = h[0]; h01.y = h[1]; h23.x = h[2]; h23.y = h[3];
    l01.x = l[0]; l01.y = l[1]; l23.x = l[2]; l23.y = l[3];
    ((__nv_bfloat162*)hi)[2*i]   = h01;
    ((__nv_bfloat162*)hi)[2*i+1] = h23;
    ((__nv_bfloat162*)lo)[2*i]   = l01;
    ((__nv_bfloat162*)lo)[2*i+1] = l23;
}

// ---------------------------------------------------------------------------
// Gate kernel (verified in rounds 6-7): softmax gates + out init
// ---------------------------------------------------------------------------
__global__ __launch_bounds__(256) void gate_kernel(
    const float* __restrict__ x, const float* __restrict__ Wg,
    const float* __restrict__ bg, const float* __restrict__ bf,
    float* __restrict__ out)
{
    __shared__ float As[16][68];
    __shared__ float Bs[16][68];
    __shared__ float Ls[64][68];

    const int tid = threadIdx.x;
    const int tx = tid & 15, ty = tid >> 4;
    const int bm = blockIdx.x * 64;
    const int lrow = tid >> 2;
    const int lkq  = (tid & 3) << 2;

    float acc[4][4];
    #pragma unroll
    for (int i = 0; i < 4; ++i)
        #pragma unroll
        for (int j = 0; j < 4; ++j) acc[i][j] = 0.f;

    const float* pA = x  + (long)(bm + lrow) * II + lkq;
    const float* pB = Wg + (long)lrow * II + lkq;

    for (int k0 = 0; k0 < II; k0 += 16) {
        float4 va = *(const float4*)(pA + k0);
        float4 vb = *(const float4*)(pB + k0);
        As[lkq+0][lrow] = va.x; As[lkq+1][lrow] = va.y;
        As[lkq+2][lrow] = va.z; As[lkq+3][lrow] = va.w;
        Bs[lkq+0][lrow] = vb.x; Bs[lkq+1][lrow] = vb.y;
        Bs[lkq+2][lrow] = vb.z; Bs[lkq+3][lrow] = vb.w;
        __syncthreads();
        #pragma unroll
        for (int kk = 0; kk < 16; ++kk) {
            float a[4], b[4];
            #pragma unroll
            for (int i = 0; i < 4; ++i) a[i] = As[kk][ty*4+i];
            #pragma unroll
            for (int j = 0; j < 4; ++j) b[j] = Bs[kk][tx*4+j];
            #pragma unroll
            for (int i = 0; i < 4; ++i)
                #pragma unroll
                for (int j = 0; j < 4; ++j)
                    acc[i][j] = fmaf(a[i], b[j], acc[i][j]);
        }
        __syncthreads();
    }

    #pragma unroll
    for (int i = 0; i < 4; ++i)
        #pragma unroll
        for (int j = 0; j < 4; ++j)
            Ls[ty*4+i][tx*4+j] = acc[i][j] + bg[tx*4+j];
    __syncthreads();

    {
        const int row = tid >> 2, t = tid & 3;
        const float* L = &Ls[row][t*16];
        float m = L[0];
        #pragma unroll
        for (int e = 1; e < 16; ++e) m = fmaxf(m, L[e]);
        float ex[16], s = 0.f;
        #pragma unroll
        for (int e = 0; e < 16; ++e) { ex[e] = __expf(L[e] - m); s += ex[e]; }
        const float inv = 1.f / s;
        const int b = bm + row;
        #pragma unroll
        for (int e = 0; e < 16; ++e)
            g_gate_buf[b*64 + t*16 + e] = ex[e] * inv;
        out[t*BB + b] = bf[t];
    }
}

// ---------------------------------------------------------------------------
// Tensor-core expert kernel via legacy mma.sync (HMMA), bf16 3-split, K'=3072.
// CTA 128x128, BK=32, 8 warps (2m x 4n), warp tile 64x32.
// Swizzled smem: tile row = 64B (32 bf16); byte off = row*64 + ((k16^((row>>1)&3))<<4)
// -> conflict-free for cp.async 16B stores and 8-row ldmatrix phases.
// ---------------------------------------------------------------------------
#define CHUNKS 96   // 3 * 1024 / 32

__device__ __forceinline__ uint32_t sw_off(int row, int k16) {
    return (uint32_t)(row*64 + (((k16) ^ ((row>>1)&3)) << 4));
}

__global__ __launch_bounds__(256, 2) void expert_mma_kernel(
    const float* __restrict__ be, const float* __restrict__ Wf,
    float* __restrict__ out)
{
    __shared__ __align__(128) char sX[2][8192];   // 128 rows x 32 bf16
    __shared__ __align__(128) char sW[2][8192];
    __shared__ float wfS[4][128];
    __shared__ float beS[128];
    __shared__ float gS[128*4];
    __shared__ float red[128*4*4];                // [row][t][wn]

    const int tid  = threadIdx.x;
    const int wid  = tid >> 5;
    const int lane = tid & 31;
    const int wm = wid >> 2, wn = wid & 3;        // 2 x 4 warps
    const int g = lane >> 2, t = lane & 3;
    const int q = lane >> 3, ln7 = lane & 7;

    const int bn = blockIdx.x * 128;
    const int bm = blockIdx.y * 128;
    const int e  = bn >> 9;
    const int h0 = bn & (HH - 1);

    // Epilogue operand fills
    for (int i = tid; i < 128; i += 256) beS[i] = be[e*HH + h0 + i];
    for (int i = tid; i < 512; i += 256) wfS[i>>7][i&127] = Wf[(i>>7)*HH + h0 + (i&127)];
    for (int i = tid; i < 512; i += 256)
        gS[i] = g_gate_buf[(bm + (i>>2))*64 + (i&3)*16 + e];

    // ldmatrix smem offsets (per-lane constants)
    uint32_t offA[4][2], offB[4][2];
    #pragma unroll
    for (int mt = 0; mt < 4; ++mt)
        #pragma unroll
        for (int ks = 0; ks < 2; ++ks) {
            const int rowA = wm*64 + mt*16 + (q&1)*8 + ln7;
            offA[mt][ks] = sw_off(rowA, 2*ks + (q>>1));
        }
    #pragma unroll
    for (int nt = 0; nt < 4; ++nt)
        #pragma unroll
        for (int ks = 0; ks < 2; ++ks) {
            const int rowB = wn*32 + nt*8 + ln7;
            offB[nt][ks] = sw_off(rowB, 2*ks + (q&1));
        }

    const uint32_t sXu = (uint32_t)__cvta_generic_to_shared(&sX[0][0]);
    const uint32_t sWu = (uint32_t)__cvta_generic_to_shared(&sW[0][0]);

    // cp.async dst offsets: thread -> rows (tid>>2) and (tid>>2)+64, 16B col tid&3
    const int lr0 = tid >> 2, lk16 = tid & 3;
    const uint32_t d0 = sw_off(lr0, lk16);          // +4096 for row+64

    float acc[4][4][4];
    #pragma unroll
    for (int a = 0; a < 4; ++a)
        #pragma unroll
        for (int b = 0; b < 4; ++b)
            #pragma unroll
            for (int k = 0; k < 4; ++k) acc[a][b][k] = 0.f;

    // async copy issue for chunk c into buffer buf
    auto issue = [&](int buf, int c) {
        const int kp = c * 32;                 // k' in [0,3072)
        const int seg = kp >> 10, k0 = kp & 1023;
        const __nv_bfloat16* A = (seg == 2) ? g_x_lo : g_x_hi;
        const __nv_bfloat16* B = (seg == 1) ? g_w_lo : g_w_hi;
        const long kelem = k0 + lk16*8;
        const char* sa0 = (const char*)(A + (long)(bm + lr0)     * II + kelem);
        const char* sa1 = (const char*)(A + (long)(bm + lr0 + 64)* II + kelem);
        const char* sb0 = (const char*)(B + (long)(bn + lr0)     * II + kelem);
        const char* sb1 = (const char*)(B + (long)(bn + lr0 + 64)* II + kelem);
        const uint32_t xb = sXu + buf*8192, wb = sWu + buf*8192;
        asm volatile("cp.async.cg.shared.global [%0], [%1], 16;" :: "r"(xb + d0),        "l"(sa0));
        asm volatile("cp.async.cg.shared.global [%0], [%1], 16;" :: "r"(xb + d0 + 4096), "l"(sa1));
        asm volatile("cp.async.cg.shared.global [%0], [%1], 16;" :: "r"(wb + d0),        "l"(sb0));
        asm volatile("cp.async.cg.shared.global [%0], [%1], 16;" :: "r"(wb + d0 + 4096), "l"(sb1));
    };

    issue(0, 0);
    asm volatile("cp.async.commit_group;");

    for (int c = 0; c < CHUNKS; ++c) {
        if (c + 1 < CHUNKS) issue((c + 1) & 1, c + 1);
        asm volatile("cp.async.commit_group;");
        asm volatile("cp.async.wait_group 1;");
        __syncthreads();

        const uint32_t xb = sXu + (c & 1)*8192, wb = sWu + (c & 1)*8192;
        #pragma unroll
        for (int ks = 0; ks < 2; ++ks) {
            uint32_t bf_[4][2];
            #pragma unroll
            for (int nt = 0; nt < 4; ++nt)
                asm volatile("ldmatrix.sync.aligned.m8n8.x2.shared.b16 {%0,%1}, [%2];"
                    : "=r"(bf_[nt][0]), "=r"(bf_[nt][1]) : "r"(wb + offB[nt][ks]));
            #pragma unroll
            for (int mt = 0; mt < 4; ++mt) {
                uint32_t a0, a1, a2, a3;
                asm volatile("ldmatrix.sync.aligned.m8n8.x4.shared.b16 {%0,%1,%2,%3}, [%4];"
                    : "=r"(a0), "=r"(a1), "=r"(a2), "=r"(a3) : "r"(xb + offA[mt][ks]));
                #pragma unroll
                for (int nt = 0; nt < 4; ++nt)
                    asm volatile(
                        "mma.sync.aligned.m16n8k16.row.col.f32.bf16.bf16.f32 "
                        "{%0,%1,%2,%3}, {%4,%5,%6,%7}, {%8,%9}, {%0,%1,%2,%3};"
                        : "+f"(acc[mt][nt][0]), "+f"(acc[mt][nt][1]),
                          "+f"(acc[mt][nt][2]), "+f"(acc[mt][nt][3])
                        : "r"(a0), "r"(a1), "r"(a2), "r"(a3),
                          "r"(bf_[nt][0]), "r"(bf_[nt][1]));
            }
        }
        __syncthreads();
    }

    // ---- Epilogue: relu(+be), dot Wf, reduce, gate, atomicAdd ----
    #pragma unroll
    for (int mt = 0; mt < 4; ++mt) {
        #pragma unroll
        for (int rs = 0; rs < 2; ++rs) {
            const int row_l = wm*64 + mt*16 + g + rs*8;
            float pt[4] = {0.f, 0.f, 0.f, 0.f};
            #pragma unroll
            for (int nt = 0; nt < 4; ++nt) {
                const int col0 = wn*32 + nt*8 + 2*t;
                float v0 = fmaxf(acc[mt][nt][rs*2+0] + beS[col0],     0.f);
                float v1 = fmaxf(acc[mt][nt][rs*2+1] + beS[col0 + 1], 0.f);
                #pragma unroll
                for (int tt = 0; tt < 4; ++tt)
                    pt[tt] += v0*wfS[tt][col0] + v1*wfS[tt][col0+1];
            }
            #pragma unroll
            for (int tt = 0; tt < 4; ++tt) {
                pt[tt] += __shfl_xor_sync(0xFFFFFFFFu, pt[tt], 1);
                pt[tt] += __shfl_xor_sync(0xFFFFFFFFu, pt[tt], 2);
            }
            if (t == 0) {
                #pragma unroll
                for (int tt = 0; tt < 4; ++tt)
                    red[(row_l*4 + tt)*4 + wn] = pt[tt];
            }
        }
    }
    __syncthreads();
    if (tid < 128) {
        const int row = tid;
        #pragma unroll
        for (int tt = 0; tt < 4; ++tt) {
            const float* r4 = &red[(row*4 + tt)*4];
            const float s = (r4[0] + r4[1]) + (r4[2] + r4[3]);
            atomicAdd(&out[tt*BB + bm + row], s * gS[row*4 + tt]);
        }
    }
}

// ---------------------------------------------------------------------------
// Launch. Inputs: x, We, be, Wg, bg, Wf, bf. Output f32 [T,B,1].
// ---------------------------------------------------------------------------
extern "C" void kernel_launch(void* const* d_in, const int* in_sizes, int n_in,
                              void* d_out, int out_size)
{
    const float* x  = (const float*)d_in[0];
    const float* We = (const float*)d_in[1];
    const float* be = (const float*)d_in[2];
    const float* Wg = (const float*)d_in[3];
    const float* bg = (const float*)d_in[4];
    const float* Wf = (const float*)d_in[5];
    const float* bf = (const float*)d_in[6];
    float* out = (float*)d_out;

    __nv_bfloat16 *xh, *xl, *wh, *wl;
    cudaGetSymbolAddress((void**)&xh, g_x_hi);
    cudaGetSymbolAddress((void**)&xl, g_x_lo);
    cudaGetSymbolAddress((void**)&wh, g_w_hi);
    cudaGetSymbolAddress((void**)&wl, g_w_lo);

    // 1) bf16 hi/lo split prepass
    split_kernel<<<(BB*II/4)/256, 256>>>(x,  xh, xl);
    split_kernel<<<(NN*II/4)/256, 256>>>(We, wh, wl);

    // 2) gates + softmax + out init
    gate_kernel<<<BB/64, 256>>>(x, Wg, bg, bf, out);

    // 3) tensor-core expert GEMM (bf16x3 via mma.sync) with fused epilogue
    dim3 grid(NN/128, BB/128);   // 64 x 64
    expert_mma_kernel<<<grid, 256>>>(be, Wf, out);
}